// round 2
// baseline (speedup 1.0000x reference)
#include <cuda_runtime.h>
#include <cstdint>
#include <cstddef>

// Problem constants
#define BB 512
#define TT 512
#define FF 64
#define PP 32
#define UU 512
#define LL 3

// Kernel config
#define RR   4              // batch rows per CTA
#define NCTA (BB / RR)      // 128 CTAs
#define NTH  256            // threads per CTA (2 output cols each -> 512)
#define KT   16             // K-tile rows staged in smem

// ---------------- cp.async helpers ----------------
__device__ __forceinline__ void cp_async16(void* s, const void* g) {
    unsigned ss = (unsigned)__cvta_generic_to_shared(s);
    asm volatile("cp.async.cg.shared.global [%0], [%1], 16;" :: "r"(ss), "l"(g));
}
__device__ __forceinline__ void cp_commit() { asm volatile("cp.async.commit_group;"); }
template <int N>
__device__ __forceinline__ void cp_wait() { asm volatile("cp.async.wait_group %0;" :: "n"(N)); }

// Stage one KT x UU fp32 weight tile into smem (KT*UU = 8192 floats = 2048 float4)
__device__ __forceinline__ void copy_tile(float* dst, const float* __restrict__ src, int tid) {
#pragma unroll
    for (int j = 0; j < (KT * UU) / (NTH * 4); ++j) {
        int idx = (tid + j * NTH) * 4;
        cp_async16(dst + idx, src + idx);
    }
}

// Accumulating 4-row mat-vec: acc[r][c] += sum_k act[r][k] * W[k][n0+c]
// W streamed from gmem (L2-resident) through a 2-stage smem pipeline.
__device__ __forceinline__ void mv_accum(float acc[RR][2],
                                         const float* __restrict__ Wg, int K,
                                         const float* __restrict__ act, int stride,
                                         float* wbuf, int tid)
{
    const int ntiles = K / KT;
    copy_tile(wbuf, Wg, tid);
    cp_commit();
    for (int tile = 0; tile < ntiles; ++tile) {
        const float* cur = wbuf + (tile & 1) * (KT * UU);
        if (tile + 1 < ntiles) {
            copy_tile(wbuf + ((tile + 1) & 1) * (KT * UU), Wg + (size_t)(tile + 1) * KT * UU, tid);
            cp_commit();
            cp_wait<1>();
        } else {
            cp_wait<0>();
        }
        __syncthreads();
        const float* a0p = act + 0 * stride + tile * KT;
        const float* a1p = act + 1 * stride + tile * KT;
        const float* a2p = act + 2 * stride + tile * KT;
        const float* a3p = act + 3 * stride + tile * KT;
        const float* wp  = cur + 2 * tid;
#pragma unroll
        for (int kk = 0; kk < KT; ++kk) {
            float2 w = *reinterpret_cast<const float2*>(wp + kk * UU);
            float a0 = a0p[kk], a1 = a1p[kk], a2 = a2p[kk], a3 = a3p[kk];
            acc[0][0] = fmaf(a0, w.x, acc[0][0]); acc[0][1] = fmaf(a0, w.y, acc[0][1]);
            acc[1][0] = fmaf(a1, w.x, acc[1][0]); acc[1][1] = fmaf(a1, w.y, acc[1][1]);
            acc[2][0] = fmaf(a2, w.x, acc[2][0]); acc[2][1] = fmaf(a2, w.y, acc[2][1]);
            acc[3][0] = fmaf(a3, w.x, acc[3][0]); acc[3][1] = fmaf(a3, w.y, acc[3][1]);
        }
        __syncthreads();
    }
}

// Shared memory layout (floats)
#define SM_HS    0                       // LL*RR*UU = 6144
#define SM_PREV  (SM_HS   + LL*RR*UU)    // RR*UU    = 2048
#define SM_IN96  (SM_PREV + RR*UU)       // RR*(FF+PP) = 384
#define SM_ACCB  (SM_IN96 + RR*(FF+PP))  // RR*PP    = 128
#define SM_WBUF  (SM_ACCB + RR*PP)       // 2*KT*UU  = 16384
#define SM_WOUT  (SM_WBUF + 2*KT*UU)     // UU*PP    = 16384
#define SM_BA    (SM_WOUT + UU*PP)       // LL*UU    = 1536
#define SM_BB0   (SM_BA   + LL*UU)       // UU       = 512
#define SM_BBR   (SM_BB0  + UU)          // (LL-1)*UU= 1024
#define SM_BC    (SM_BBR  + (LL-1)*UU)   // LL*UU    = 1536
#define SM_BOUT  (SM_BC   + LL*UU)       // PP       = 32
#define SM_TOTAL (SM_BOUT + PP)          // 46112 floats = 184448 B

extern "C" __global__ void __launch_bounds__(NTH, 1)
accrnn_kernel(const float* __restrict__ x,
              const float* __restrict__ WA,  const float* __restrict__ bA,
              const float* __restrict__ WB0, const float* __restrict__ bB0,
              const float* __restrict__ WBr, const float* __restrict__ bBr,
              const float* __restrict__ WC,  const float* __restrict__ bC,
              const float* __restrict__ Wout, const float* __restrict__ bout,
              float* __restrict__ out)
{
    extern __shared__ __align__(16) float sm[];
    float* hs    = sm + SM_HS;
    float* prev  = sm + SM_PREV;
    float* in96  = sm + SM_IN96;
    float* accb  = sm + SM_ACCB;
    float* wbuf  = sm + SM_WBUF;
    float* wouts = sm + SM_WOUT;
    float* sbA   = sm + SM_BA;
    float* sbB0  = sm + SM_BB0;
    float* sbBr  = sm + SM_BBR;
    float* sbC   = sm + SM_BC;
    float* sbout = sm + SM_BOUT;

    const int tid  = threadIdx.x;
    const int row0 = blockIdx.x * RR;
    const int n0   = 2 * tid;

    // ---- one-time preload into smem ----
    for (int i = tid; i < UU * PP;      i += NTH) wouts[i] = Wout[i];
    for (int i = tid; i < LL * UU;      i += NTH) sbA[i]   = bA[i];
    for (int i = tid; i < UU;           i += NTH) sbB0[i]  = bB0[i];
    for (int i = tid; i < (LL-1) * UU;  i += NTH) sbBr[i]  = bBr[i];
    for (int i = tid; i < LL * UU;      i += NTH) sbC[i]   = bC[i];
    if (tid < PP) sbout[tid] = bout[tid];
    for (int i = tid; i < LL * RR * UU; i += NTH) hs[i]    = 0.f;
    for (int i = tid; i < RR * PP;      i += NTH) accb[i]  = 0.f;
    __syncthreads();

    for (int t = 0; t < TT; ++t) {
        // ---- build concat input [x_t | acc] : [RR][96] ----
        {
            int r = tid >> 6, f = tid & 63;
            in96[r * (FF + PP) + f] = x[((size_t)(row0 + r) * TT + t) * FF + f];
            if (tid < RR * PP) {
                int r2 = tid >> 5, p = tid & 31;
                in96[r2 * (FF + PP) + FF + p] = accb[r2 * PP + p];
            }
        }
        __syncthreads();

        const float* pact = in96;
        int pstride = FF + PP;

        for (int i = 0; i < LL; ++i) {
            // fused: new_state = hs_i @ WA_i + prev @ WB_i + biases
            float acc[RR][2];
            float b0 = sbA[i * UU + n0]     + ((i == 0) ? sbB0[n0]     : sbBr[(i-1) * UU + n0]);
            float b1 = sbA[i * UU + n0 + 1] + ((i == 0) ? sbB0[n0 + 1] : sbBr[(i-1) * UU + n0 + 1]);
#pragma unroll
            for (int r = 0; r < RR; ++r) { acc[r][0] = b0; acc[r][1] = b1; }

            mv_accum(acc, WA + (size_t)i * UU * UU, UU, hs + i * RR * UU, UU, wbuf, tid);
            if (i == 0)
                mv_accum(acc, WB0, FF + PP, pact, pstride, wbuf, tid);
            else
                mv_accum(acc, WBr + (size_t)(i - 1) * UU * UU, UU, pact, pstride, wbuf, tid);

            // mv_accum ends with __syncthreads(): everyone is done reading old hs_i.
            float* hsi = hs + i * RR * UU;
#pragma unroll
            for (int r = 0; r < RR; ++r) {
                hsi[r * UU + n0]     = acc[r][0];
                hsi[r * UU + n0 + 1] = acc[r][1];
            }
            __syncthreads();

            // prev = new_state @ WC_i + bC_i
            float acc2[RR][2];
#pragma unroll
            for (int r = 0; r < RR; ++r) {
                acc2[r][0] = sbC[i * UU + n0];
                acc2[r][1] = sbC[i * UU + n0 + 1];
            }
            mv_accum(acc2, WC + (size_t)i * UU * UU, UU, hsi, UU, wbuf, tid);
#pragma unroll
            for (int r = 0; r < RR; ++r) {
                prev[r * UU + n0]     = acc2[r][0];
                prev[r * UU + n0 + 1] = acc2[r][1];
            }
            __syncthreads();
            pact = prev;
            pstride = UU;
        }

        // ---- output: res = prev @ Wout + bout ; acc += res ; store res ----
        if (tid < RR * PP) {
            int r = tid >> 5, p = tid & 31;
            float s = sbout[p];
            const float* pr = prev + r * UU;
#pragma unroll 8
            for (int k = 0; k < UU; ++k)
                s = fmaf(pr[k], wouts[k * PP + p], s);
            accb[r * PP + p] += s;
            out[((size_t)(row0 + r) * TT + t) * PP + p] = s;
        }
        __syncthreads();
    }
}

extern "C" void kernel_launch(void* const* d_in, const int* in_sizes, int n_in,
                              void* d_out, int out_size)
{
    const float* x    = (const float*)d_in[0];
    const float* WA   = (const float*)d_in[1];
    const float* bA   = (const float*)d_in[2];
    const float* WB0  = (const float*)d_in[3];
    const float* bB0  = (const float*)d_in[4];
    const float* WBr  = (const float*)d_in[5];
    const float* bBr  = (const float*)d_in[6];
    const float* WC   = (const float*)d_in[7];
    const float* bC   = (const float*)d_in[8];
    const float* Wout = (const float*)d_in[9];
    const float* bout = (const float*)d_in[10];
    float* out = (float*)d_out;

    size_t smem = (size_t)SM_TOTAL * sizeof(float);
    cudaFuncSetAttribute(accrnn_kernel, cudaFuncAttributeMaxDynamicSharedMemorySize, (int)smem);
    accrnn_kernel<<<NCTA, NTH, smem>>>(x, WA, bA, WB0, bB0, WBr, bBr, WC, bC, Wout, bout, out);
}

// round 4
// speedup vs baseline: 1.2146x; 1.2146x over previous
#include <cuda_runtime.h>
#include <cstdint>
#include <cstddef>

// Problem constants
#define BB 512
#define TT 512
#define FF 64
#define PP 32
#define UU 512
#define LL 3

// Kernel config
#define CS   2                 // cluster size (CTAs)
#define RR   8                 // batch rows per cluster
#define HALF 256               // output columns per CTA (UU / CS)
#define NTH  128               // threads per CTA: 2 cols x 8 rows each
#define KT   32                // K-tile rows staged in smem
#define NCTA ((BB / RR) * CS)  // 128 CTAs = 64 clusters

typedef unsigned long long u64;

// ---------------- packed f32x2 helpers ----------------
__device__ __forceinline__ void fma2(u64& d, u64 a, u64 b) {
    asm("fma.rn.f32x2 %0, %1, %2, %0;" : "+l"(d) : "l"(a), "l"(b));
}
__device__ __forceinline__ u64 pack2(float x, float y) {
    u64 r;
    asm("mov.b64 %0, {%1, %2};" : "=l"(r)
        : "r"(__float_as_uint(x)), "r"(__float_as_uint(y)));
    return r;
}
__device__ __forceinline__ float2 unpack2(u64 v) {
    unsigned lo, hi;
    asm("mov.b64 {%0, %1}, %2;" : "=r"(lo), "=r"(hi) : "l"(v));
    return make_float2(__uint_as_float(lo), __uint_as_float(hi));
}

// ---------------- cluster helpers ----------------
__device__ __forceinline__ void cluster_sync() {
    asm volatile("barrier.cluster.arrive.aligned;" ::: "memory");
    asm volatile("barrier.cluster.wait.aligned;" ::: "memory");
}
__device__ __forceinline__ unsigned ctarank() {
    unsigned r; asm("mov.u32 %0, %%cluster_ctarank;" : "=r"(r)); return r;
}
__device__ __forceinline__ unsigned mapa_u32(unsigned addr, unsigned rank) {
    unsigned r;
    asm("mapa.shared::cluster.u32 %0, %1, %2;" : "=r"(r) : "r"(addr), "r"(rank));
    return r;
}
__device__ __forceinline__ void st_cluster_u64(unsigned raddr, u64 v) {
    asm volatile("st.shared::cluster.u64 [%0], %1;" :: "r"(raddr), "l"(v));
}

// ---------------- cp.async helpers ----------------
__device__ __forceinline__ void cp_async16(void* s, const void* g) {
    unsigned ss = (unsigned)__cvta_generic_to_shared(s);
    asm volatile("cp.async.cg.shared.global [%0], [%1], 16;" :: "r"(ss), "l"(g));
}
__device__ __forceinline__ void cp_commit() { asm volatile("cp.async.commit_group;"); }
template <int N>
__device__ __forceinline__ void cp_wait() { asm volatile("cp.async.wait_group %0;" :: "n"(N)); }

// Stage KT x HALF fp32 weight slice (rows stride UU in gmem) into smem.
// KT*HALF = 8192 floats = 2048 float4 -> 16 chunks per thread.
__device__ __forceinline__ void stage(float* dst, const float* __restrict__ src, int tid) {
#pragma unroll
    for (int j = 0; j < (KT * HALF) / (NTH * 4); ++j) {
        int idx = tid + j * NTH;          // [0, 2048)
        int krow = idx >> 6;              // 64 float4 per k-row
        int c4   = idx & 63;
        cp_async16(dst + krow * HALF + c4 * 4, src + (size_t)krow * UU + c4 * 4);
    }
}

// acc[cc][j]: column (c0+cc), row-pair (2j,2j+1). act layout: [k][RR rows].
// W streamed from gmem (col-slice, L2-resident) via 2-stage cp.async pipeline.
__device__ __forceinline__ void mv(u64 acc[2][4], const float* __restrict__ Wg, int K,
                                   const float* __restrict__ act, float* wbuf, int tid)
{
    const int nt = K / KT;
    stage(wbuf, Wg, tid);
    cp_commit();
    for (int t = 0; t < nt; ++t) {
        const float* cur = wbuf + (t & 1) * (KT * HALF);
        if (t + 1 < nt) {
            stage(wbuf + ((t + 1) & 1) * (KT * HALF), Wg + (size_t)(t + 1) * KT * UU, tid);
            cp_commit();
            cp_wait<1>();
        } else {
            cp_wait<0>();
        }
        __syncthreads();
        const float* wp = cur + 2 * tid;
        const float* ap = act + t * KT * RR;
#pragma unroll 8
        for (int kk = 0; kk < KT; ++kk) {
            float2 w = *reinterpret_cast<const float2*>(wp + kk * HALF);
            const u64* av = reinterpret_cast<const u64*>(ap + kk * RR);
            u64 a0 = av[0], a1 = av[1], a2 = av[2], a3 = av[3];   // broadcast LDS
            u64 w0 = pack2(w.x, w.x);
            u64 w1 = pack2(w.y, w.y);
            fma2(acc[0][0], a0, w0); fma2(acc[0][1], a1, w0);
            fma2(acc[0][2], a2, w0); fma2(acc[0][3], a3, w0);
            fma2(acc[1][0], a0, w1); fma2(acc[1][1], a1, w1);
            fma2(acc[1][2], a2, w1); fma2(acc[1][3], a3, w1);
        }
        __syncthreads();
    }
}

// Shared memory layout (floats)
#define SM_HS    0                        // LL*UU*RR = 12288   ([layer][col][row])
#define SM_PREV  (SM_HS   + LL*UU*RR)     // UU*RR    = 4096    ([col][row])
#define SM_IN96  (SM_PREV + UU*RR)        // (FF+PP)*RR = 768   ([k][row]; tail = running acc)
#define SM_WBUF  (SM_IN96 + (FF+PP)*RR)   // 2*KT*HALF = 16384
#define SM_WOUT  (SM_WBUF + 2*KT*HALF)    // UU*PP    = 16384
#define SM_BAB   (SM_WOUT + UU*PP)        // LL*HALF  = 768     (bA + bB, own col slice)
#define SM_BC    (SM_BAB  + LL*HALF)      // LL*HALF  = 768
#define SM_BOUT  (SM_BC   + LL*HALF)      // PP       = 32
#define SM_TOTAL (SM_BOUT + PP)           // 51488 floats = 205952 B

extern "C" __global__ void __launch_bounds__(NTH, 1) __cluster_dims__(CS, 1, 1)
accrnn_kernel(const float* __restrict__ x,
              const float* __restrict__ WA,  const float* __restrict__ bA,
              const float* __restrict__ WB0, const float* __restrict__ bB0,
              const float* __restrict__ WBr, const float* __restrict__ bBr,
              const float* __restrict__ WC,  const float* __restrict__ bC,
              const float* __restrict__ Wout, const float* __restrict__ bout,
              float* __restrict__ out)
{
    extern __shared__ __align__(16) float sm[];
    float* hs    = sm + SM_HS;
    float* prev  = sm + SM_PREV;
    float* in96  = sm + SM_IN96;
    float* wbuf  = sm + SM_WBUF;
    float* wouts = sm + SM_WOUT;
    float* sAB   = sm + SM_BAB;
    float* sC    = sm + SM_BC;
    float* sout  = sm + SM_BOUT;

    const int tid   = threadIdx.x;
    const unsigned rank  = ctarank();
    const unsigned prank = rank ^ 1u;
    const int row0  = (blockIdx.x / CS) * RR;
    const int coff  = (int)rank * HALF;

    const unsigned sbase = (unsigned)__cvta_generic_to_shared(sm);
    const unsigned rbase = mapa_u32(sbase, prank);   // peer CTA smem base

    // ---- one-time preload ----
    for (int i = tid; i < UU * PP; i += NTH) wouts[i] = Wout[i];
    for (int l = 0; l < LL; ++l)
        for (int j = tid; j < HALF; j += NTH) {
            int c = coff + j;
            sAB[l * HALF + j] = bA[l * UU + c] + (l == 0 ? bB0[c] : bBr[(l - 1) * UU + c]);
            sC[l * HALF + j]  = bC[l * UU + c];
        }
    if (tid < PP) sout[tid] = bout[tid];
    for (int i = tid; i < LL * UU * RR; i += NTH) hs[i] = 0.f;
    for (int i = tid; i < (FF + PP) * RR; i += NTH) in96[i] = 0.f;
    __syncthreads();
    cluster_sync();

    for (int t = 0; t < TT; ++t) {
        // ---- x part of concat input, layout [f][row] ----
#pragma unroll
        for (int j = 0; j < (RR * FF) / NTH; ++j) {
            int idx = tid + j * NTH;
            int r = idx >> 6, f = idx & 63;
            in96[f * RR + r] = x[((size_t)(row0 + r) * TT + t) * FF + f];
        }
        // (mv's internal __syncthreads orders these writes before reads)

        const float* actB = in96;
        int KB = FF + PP;

        for (int l = 0; l < LL; ++l) {
            // ---- new_state slice = hs_l @ WA_l + actB @ WB_l + biases ----
            u64 acc[2][4];
            {
                float b0 = sAB[l * HALF + 2 * tid];
                float b1 = sAB[l * HALF + 2 * tid + 1];
                u64 p0 = pack2(b0, b0), p1 = pack2(b1, b1);
                acc[0][0] = acc[0][1] = acc[0][2] = acc[0][3] = p0;
                acc[1][0] = acc[1][1] = acc[1][2] = acc[1][3] = p1;
            }
            float* hl = hs + l * UU * RR;
            mv(acc, WA + (size_t)l * UU * UU + coff, UU, hl, wbuf, tid);
            if (l == 0) mv(acc, WB0 + coff, KB, actB, wbuf, tid);
            else        mv(acc, WBr + (size_t)(l - 1) * UU * UU + coff, UU, actB, wbuf, tid);

            cluster_sync();   // all reads of hs_l / actB complete cluster-wide

            // write new state slice: local + remote (peer gets our columns)
            const unsigned hoff = (unsigned)((SM_HS + l * UU * RR) * sizeof(float));
#pragma unroll
            for (int cc = 0; cc < 2; ++cc) {
                int c = coff + 2 * tid + cc;
                float* dst = hs + l * UU * RR + c * RR;
                unsigned roff = rbase + hoff + (unsigned)(c * RR * sizeof(float));
#pragma unroll
                for (int j = 0; j < 4; ++j) {
                    *reinterpret_cast<u64*>(dst + 2 * j) = acc[cc][j];
                    st_cluster_u64(roff + (unsigned)(2 * j * sizeof(float)), acc[cc][j]);
                }
            }
            cluster_sync();   // new hs_l visible in both CTAs

            // ---- prev slice = new_state @ WC_l + bC_l ----
            u64 acc2[2][4];
            {
                float b0 = sC[l * HALF + 2 * tid];
                float b1 = sC[l * HALF + 2 * tid + 1];
                u64 p0 = pack2(b0, b0), p1 = pack2(b1, b1);
                acc2[0][0] = acc2[0][1] = acc2[0][2] = acc2[0][3] = p0;
                acc2[1][0] = acc2[1][1] = acc2[1][2] = acc2[1][3] = p1;
            }
            mv(acc2, WC + (size_t)l * UU * UU + coff, UU, hl, wbuf, tid);

            const unsigned poff = (unsigned)(SM_PREV * sizeof(float));
#pragma unroll
            for (int cc = 0; cc < 2; ++cc) {
                int c = coff + 2 * tid + cc;
                float* dst = prev + c * RR;
                unsigned roff = rbase + poff + (unsigned)(c * RR * sizeof(float));
#pragma unroll
                for (int j = 0; j < 4; ++j) {
                    *reinterpret_cast<u64*>(dst + 2 * j) = acc2[cc][j];
                    st_cluster_u64(roff + (unsigned)(2 * j * sizeof(float)), acc2[cc][j]);
                }
            }
            cluster_sync();   // prev visible in both CTAs

            actB = prev;
            KB = UU;
        }

        // ---- res = prev @ Wout + bout ; acc += res ; store res (rank 0) ----
        {
            int r = tid >> 4, pp = tid & 15, cc = 2 * pp;
            u64 acc = pack2(sout[cc], sout[cc + 1]);
#pragma unroll 8
            for (int k = 0; k < UU; ++k) {
                float pv = prev[k * RR + r];
                u64 w = *reinterpret_cast<const u64*>(wouts + k * PP + cc);
                fma2(acc, pack2(pv, pv), w);
            }
            float2 res = unpack2(acc);
            in96[(FF + cc) * RR + r]     += res.x;   // running accumulator (concat tail)
            in96[(FF + cc + 1) * RR + r] += res.y;
            if (rank == 0) {
                *reinterpret_cast<float2*>(out + ((size_t)(row0 + r) * TT + t) * PP + cc) =
                    res;
            }
        }
        __syncthreads();
    }
}

extern "C" void kernel_launch(void* const* d_in, const int* in_sizes, int n_in,
                              void* d_out, int out_size)
{
    const float* x    = (const float*)d_in[0];
    const float* WA   = (const float*)d_in[1];
    const float* bA   = (const float*)d_in[2];
    const float* WB0  = (const float*)d_in[3];
    const float* bB0  = (const float*)d_in[4];
    const float* WBr  = (const float*)d_in[5];
    const float* bBr  = (const float*)d_in[6];
    const float* WC   = (const float*)d_in[7];
    const float* bC   = (const float*)d_in[8];
    const float* Wout = (const float*)d_in[9];
    const float* bout = (const float*)d_in[10];
    float* out = (float*)d_out;

    size_t smem = (size_t)SM_TOTAL * sizeof(float);
    cudaFuncSetAttribute(accrnn_kernel, cudaFuncAttributeMaxDynamicSharedMemorySize, (int)smem);
    accrnn_kernel<<<NCTA, NTH, smem>>>(x, WA, bA, WB0, bB0, WBr, bBr, WC, bC, Wout, bout, out);
}

// round 5
// speedup vs baseline: 1.2900x; 1.0621x over previous
#include <cuda_runtime.h>
#include <cstdint>
#include <cstddef>

// Problem constants
#define BB 512
#define TT 512
#define FF 64
#define PP 32
#define UU 512
#define LL 3

// Kernel config
#define CS   2                 // cluster size (CTAs)
#define RR   8                 // batch rows per cluster
#define HALF 256               // output columns per CTA (UU / CS)
#define NTH  256               // threads: 128 col-pairs x 2 row-halves
#define NCTA ((BB / RR) * CS)  // 128 CTAs = 64 clusters

typedef unsigned long long u64;

// ---------------- packed f32x2 helpers ----------------
__device__ __forceinline__ void fma2(u64& d, u64 a, u64 b) {
    asm("fma.rn.f32x2 %0, %1, %2, %0;" : "+l"(d) : "l"(a), "l"(b));
}
__device__ __forceinline__ u64 pack2(float x, float y) {
    u64 r;
    asm("mov.b64 %0, {%1, %2};" : "=l"(r)
        : "r"(__float_as_uint(x)), "r"(__float_as_uint(y)));
    return r;
}

// ---------------- cluster helpers ----------------
__device__ __forceinline__ void cluster_sync() {
    asm volatile("barrier.cluster.arrive.aligned;" ::: "memory");
    asm volatile("barrier.cluster.wait.aligned;" ::: "memory");
}
__device__ __forceinline__ unsigned ctarank() {
    unsigned r; asm("mov.u32 %0, %%cluster_ctarank;" : "=r"(r)); return r;
}
__device__ __forceinline__ unsigned mapa_u32(unsigned addr, unsigned rank) {
    unsigned r;
    asm("mapa.shared::cluster.u32 %0, %1, %2;" : "=r"(r) : "r"(addr), "r"(rank));
    return r;
}
__device__ __forceinline__ void st_cluster_u64(unsigned raddr, u64 v) {
    asm volatile("st.shared::cluster.u64 [%0], %1;" :: "r"(raddr), "l"(v));
}

// Accumulating mat-vec slice. Thread owns 2 columns (cp2, cp2+1 within this
// CTA's HALF-col slice) x 4 rows (rh4..rh4+3). Weights direct LDG from L2
// (each warp: one 128B line per k). Activations act[k][RR] in smem, LDS.128.
// acc[cc][j]: column cc, row-pair j.
template<int K>
__device__ __forceinline__ void mv(u64 acc[2][2], const float* __restrict__ Wg,
                                   const float* __restrict__ act, int cp2, int rh4)
{
#pragma unroll 16
    for (int k = 0; k < K; ++k) {
        float2 w = *reinterpret_cast<const float2*>(Wg + (size_t)k * UU + cp2);
        ulonglong2 a = *reinterpret_cast<const ulonglong2*>(act + k * RR + rh4);
        u64 wx = pack2(w.x, w.x);
        u64 wy = pack2(w.y, w.y);
        fma2(acc[0][0], a.x, wx); fma2(acc[0][1], a.y, wx);
        fma2(acc[1][0], a.x, wy); fma2(acc[1][1], a.y, wy);
    }
}

// Write 2 cols x 4 rows to local buffer + peer CTA's mirror (DSMEM).
__device__ __forceinline__ void writeback(const u64 acc[2][2], float* lbuf,
                                          unsigned rbuf, int c0, int rh4)
{
#pragma unroll
    for (int cc = 0; cc < 2; ++cc) {
        int c = c0 + cc;
        u64* d = reinterpret_cast<u64*>(lbuf + c * RR + rh4);
        d[0] = acc[cc][0];
        d[1] = acc[cc][1];
        unsigned ra = rbuf + (unsigned)((c * RR + rh4) * sizeof(float));
        st_cluster_u64(ra,     acc[cc][0]);
        st_cluster_u64(ra + 8, acc[cc][1]);
    }
}

// Shared memory layout (floats)
#define SM_HS    0                        // LL*UU*RR = 12288   ([layer][col][row])
#define SM_PREV  (SM_HS   + LL*UU*RR)     // UU*RR    = 4096    ([col][row])
#define SM_IN96  (SM_PREV + UU*RR)        // (FF+PP)*RR = 768   ([k][row]; tail = running acc)
#define SM_WOUT  (SM_IN96 + (FF+PP)*RR)   // UU*PP    = 16384
#define SM_BAB   (SM_WOUT + UU*PP)        // LL*HALF  = 768  (bA+bB, own col slice)
#define SM_BC    (SM_BAB  + LL*HALF)      // LL*HALF  = 768
#define SM_BOUT  (SM_BC   + LL*HALF)      // PP       = 32
#define SM_TOTAL (SM_BOUT + PP)           // 35104 floats = 140416 B

extern "C" __global__ void __launch_bounds__(NTH, 1) __cluster_dims__(CS, 1, 1)
accrnn_kernel(const float* __restrict__ x,
              const float* __restrict__ WA,  const float* __restrict__ bA,
              const float* __restrict__ WB0, const float* __restrict__ bB0,
              const float* __restrict__ WBr, const float* __restrict__ bBr,
              const float* __restrict__ WC,  const float* __restrict__ bC,
              const float* __restrict__ Wout, const float* __restrict__ bout,
              float* __restrict__ out)
{
    extern __shared__ __align__(16) float sm[];
    float* hs    = sm + SM_HS;
    float* prev  = sm + SM_PREV;
    float* in96  = sm + SM_IN96;
    float* wouts = sm + SM_WOUT;
    float* sAB   = sm + SM_BAB;
    float* sC    = sm + SM_BC;
    float* sout  = sm + SM_BOUT;

    const int tid  = threadIdx.x;
    const int cp2  = (tid >> 1) * 2;       // column pair base within slice
    const int rh4  = (tid & 1) * 4;        // row-half base
    const unsigned rank  = ctarank();
    const unsigned prank = rank ^ 1u;
    const int row0 = (blockIdx.x / CS) * RR;
    const int coff = (int)rank * HALF;
    const int c0   = coff + cp2;           // absolute column base

    const unsigned sbase = (unsigned)__cvta_generic_to_shared(sm);
    const unsigned rbase = mapa_u32(sbase, prank);
    const unsigned rprev = rbase + (unsigned)(SM_PREV * sizeof(float));

    // ---- one-time preload ----
    for (int i = tid; i < UU * PP; i += NTH) wouts[i] = Wout[i];
    for (int l = 0; l < LL; ++l)
        for (int j = tid; j < HALF; j += NTH) {
            int c = coff + j;
            sAB[l * HALF + j] = bA[l * UU + c] + (l == 0 ? bB0[c] : bBr[(l - 1) * UU + c]);
            sC[l * HALF + j]  = bC[l * UU + c];
        }
    if (tid < PP) sout[tid] = bout[tid];
    for (int i = tid; i < LL * UU * RR; i += NTH) hs[i] = 0.f;
    for (int i = tid; i < (FF + PP) * RR; i += NTH) in96[i] = 0.f;
    __syncthreads();
    cluster_sync();

    for (int t = 0; t < TT; ++t) {
        // ---- x part of concat input, layout [f][row] ----
#pragma unroll
        for (int j = 0; j < (RR * FF) / NTH; ++j) {
            int idx = tid + j * NTH;
            int f = idx & 63, r = idx >> 6;
            in96[f * RR + r] = x[((size_t)(row0 + r) * TT + t) * FF + f];
        }
        __syncthreads();   // also covers prior-step tail (acc) writes

        const float* actB = in96;

        for (int l = 0; l < LL; ++l) {
            // ---- new_state slice = hs_l @ WA_l + actB @ WB_l + biases ----
            u64 acc[2][2];
            {
                float b0 = sAB[l * HALF + cp2];
                float b1 = sAB[l * HALF + cp2 + 1];
                acc[0][0] = acc[0][1] = pack2(b0, b0);
                acc[1][0] = acc[1][1] = pack2(b1, b1);
            }
            float* hl = hs + l * UU * RR;
            mv<UU>(acc, WA + (size_t)l * UU * UU + coff, hl, cp2, rh4);
            if (l == 0) mv<FF + PP>(acc, WB0 + coff, actB, cp2, rh4);
            else        mv<UU>(acc, WBr + (size_t)(l - 1) * UU * UU + coff, actB, cp2, rh4);

            cluster_sync();   // all reads of hs_l / actB complete cluster-wide
            writeback(acc, hl,
                      rbase + (unsigned)((SM_HS + l * UU * RR) * sizeof(float)),
                      c0, rh4);
            cluster_sync();   // new hs_l visible in both CTAs

            // ---- prev slice = new_state @ WC_l + bC_l ----
            u64 acc2[2][2];
            {
                float b0 = sC[l * HALF + cp2];
                float b1 = sC[l * HALF + cp2 + 1];
                acc2[0][0] = acc2[0][1] = pack2(b0, b0);
                acc2[1][0] = acc2[1][1] = pack2(b1, b1);
            }
            mv<UU>(acc2, WC + (size_t)l * UU * UU + coff, hl, cp2, rh4);
            writeback(acc2, prev, rprev, c0, rh4);
            cluster_sync();   // prev visible in both CTAs

            actB = prev;
        }

        // ---- res = prev @ Wout + bout ; acc += res ; store res ----
        {
            int r = tid >> 5, p = tid & 31;
            float s0 = sout[p], s1 = 0.f;
#pragma unroll 8
            for (int k = 0; k < UU; k += 2) {
                s0 = fmaf(prev[k * RR + r],       wouts[k * PP + p],       s0);
                s1 = fmaf(prev[(k + 1) * RR + r], wouts[(k + 1) * PP + p], s1);
            }
            float res = s0 + s1;
            in96[(FF + p) * RR + r] += res;   // running accumulator (concat tail)
            if (rank == 0)
                out[((size_t)(row0 + r) * TT + t) * PP + p] = res;
        }
        // next iteration's __syncthreads orders tail writes before layer-0 reads
    }
}

extern "C" void kernel_launch(void* const* d_in, const int* in_sizes, int n_in,
                              void* d_out, int out_size)
{
    const float* x    = (const float*)d_in[0];
    const float* WA   = (const float*)d_in[1];
    const float* bA   = (const float*)d_in[2];
    const float* WB0  = (const float*)d_in[3];
    const float* bB0  = (const float*)d_in[4];
    const float* WBr  = (const float*)d_in[5];
    const float* bBr  = (const float*)d_in[6];
    const float* WC   = (const float*)d_in[7];
    const float* bC   = (const float*)d_in[8];
    const float* Wout = (const float*)d_in[9];
    const float* bout = (const float*)d_in[10];
    float* out = (float*)d_out;

    size_t smem = (size_t)SM_TOTAL * sizeof(float);
    cudaFuncSetAttribute(accrnn_kernel, cudaFuncAttributeMaxDynamicSharedMemorySize, (int)smem);
    accrnn_kernel<<<NCTA, NTH, smem>>>(x, WA, bA, WB0, bB0, WBr, bBr, WC, bC, Wout, bout, out);
}